// round 5
// baseline (speedup 1.0000x reference)
#include <cuda_runtime.h>
#include <math_constants.h>

#define TOPK 9
#define BINS 32            // 32x32 grid over [0,1024)^2, cell = 32px
#define NBINS (BINS * BINS)
#define INV_CELL 0.03125f  // 1/32
#define MAXN 131072
#define MAXG 256
#define SMAX 8             // max slices per GT
#define TARGET 1024        // candidates per slice block
#define MAXTASKS (MAXG * SMAX)
#define MT 256             // threads per slice block

// ---------------- device scratch (no allocs allowed) ----------------
// Zero at module load; merge_kernel's tail re-zeros mutable state per replay.
__device__ int      g_bin_count[NBINS];
__device__ int      g_bin_start[NBINS + 1];
__device__ int      g_bin_cursor[NBINS];
__device__ float4   g_sorted[MAXN];
__device__ int      g_sorted_idx[MAXN];
__device__ unsigned g_maxw_bits, g_maxh_bits;
__device__ float    g_pv[MAXG * SMAX * TOPK];   // partial top-9 values
__device__ int      g_pi[MAXG * SMAX * TOPK];   // partial top-9 indices
__device__ int      g_task[MAXTASKS];           // (g<<4)|slice
__device__ int      g_nsl[MAXG];
__device__ int4     g_win[MAXG];                // bx0,bx1,by0,by1
__device__ int      g_total;

// ---------------- pass 1: zero w + smem histogram + max extents ----------------
__global__ __launch_bounds__(256) void count_kernel(
    const float* __restrict__ preds, float* __restrict__ w, int N)
{
    __shared__ int hist[NBINS];
    __shared__ unsigned s_mw, s_mh;
    int tid = threadIdx.x;
#pragma unroll
    for (int i = 0; i < NBINS / 256; i++) hist[tid + i * 256] = 0;
    if (tid == 0) { s_mw = 0u; s_mh = 0u; }
    __syncthreads();

    int n = blockIdx.x * 256 + tid;
    unsigned mw = 0u, mh = 0u;
    if (n < N) {
        w[n] = 0.0f;   // replaces a memset launch
        float4 b = ((const float4*)preds)[n];
        int bx = min(BINS - 1, (int)(b.x * INV_CELL));
        int by = min(BINS - 1, (int)(b.y * INV_CELL));
        atomicAdd(&hist[by * BINS + bx], 1);
        mw = __float_as_uint(b.z - b.x);   // sizes > 0: uint cmp == float cmp
        mh = __float_as_uint(b.w - b.y);
    }
#pragma unroll
    for (int off = 16; off > 0; off >>= 1) {
        mw = max(mw, __shfl_down_sync(0xffffffffu, mw, off));
        mh = max(mh, __shfl_down_sync(0xffffffffu, mh, off));
    }
    if ((tid & 31) == 0) { atomicMax(&s_mw, mw); atomicMax(&s_mh, mh); }
    __syncthreads();

#pragma unroll
    for (int i = 0; i < NBINS / 256; i++) {
        int c = hist[tid + i * 256];
        if (c > 0) atomicAdd(&g_bin_count[tid + i * 256], c);
    }
    if (tid == 0) {
        atomicMax(&g_maxw_bits, s_mw);
        atomicMax(&g_maxh_bits, s_mh);
    }
}

// ---------------- pass 2: bin scan + per-GT window/slice setup + task table ----
__global__ __launch_bounds__(NBINS) void scan_setup_kernel(
    const float* __restrict__ gtb, int G)
{
    __shared__ int sh[NBINS];
    const int t    = threadIdx.x;
    const int lane = t & 31;
    const int warp = t >> 5;

    int c = g_bin_count[t];
    sh[t] = c;
    __syncthreads();
    for (int off = 1; off < NBINS; off <<= 1) {
        int v = (t >= off) ? sh[t - off] : 0;
        __syncthreads();
        sh[t] += v;                      // inclusive scan
        __syncthreads();
    }
    int incl = sh[t];
    g_bin_start[t] = incl - c;
    g_bin_cursor[t] = incl - c;
    if (t == NBINS - 1) g_bin_start[NBINS] = incl;

    // ---- per-GT window + candidate count + slice count (threads 0..255) ----
    int nsl = 0;
    int4 win = make_int4(0, 0, 0, 0);
    if (t < G) {
        float gx1 = gtb[t * 4 + 0];
        float gy1 = gtb[t * 4 + 1];
        float gx2 = gtb[t * 4 + 2];
        float gy2 = gtb[t * 4 + 3];
        float maxw = __uint_as_float(g_maxw_bits);
        float maxh = __uint_as_float(g_maxh_bits);
        int bx0 = max(0, (int)floorf((gx1 - maxw) * INV_CELL));
        int bx1 = min(BINS - 1, (int)(gx2 * INV_CELL));
        int by0 = max(0, (int)floorf((gy1 - maxh) * INV_CELL));
        int by1 = min(BINS - 1, (int)(gy2 * INV_CELL));
        win = make_int4(bx0, bx1, by0, by1);
        int cnt = 0;
        for (int by = by0; by <= by1; by++) {
            int hi = sh[by * BINS + bx1];                              // excl start at bx1+1
            int lo = (by * BINS + bx0 == 0) ? 0 : sh[by * BINS + bx0 - 1];
            cnt += hi - lo;
        }
        nsl = min(SMAX, max(1, (cnt + TARGET - 1) / TARGET));
        g_nsl[t] = nsl;
        g_win[t] = win;
    }

    // ---- prefix sum of nsl over first 256 threads -> task table ----
    __shared__ int wsum[32];
    int v = nsl;
#pragma unroll
    for (int off = 1; off < 32; off <<= 1) {
        int u = __shfl_up_sync(0xffffffffu, v, off);
        if (lane >= off) v += u;
    }
    if (lane == 31) wsum[warp] = v;
    __syncthreads();
    if (warp == 0) {
        int u = wsum[lane];
#pragma unroll
        for (int off = 1; off < 32; off <<= 1) {
            int uu = __shfl_up_sync(0xffffffffu, u, off);
            if (lane >= off) u += uu;
        }
        wsum[lane] = u;
    }
    __syncthreads();
    if (t < 256) {
        int incl_s = v + (warp > 0 ? wsum[warp - 1] : 0);
        int excl_s = incl_s - nsl;
        for (int j = 0; j < nsl; j++)
            g_task[excl_s + j] = (t << 4) | j;
        if (t == 255) g_total = incl_s;
    }
}

// ---------------- pass 3: scatter preds into bin-sorted order ----------------
__global__ __launch_bounds__(256) void scatter_kernel(const float* __restrict__ preds, int N) {
    int n = blockIdx.x * 256 + threadIdx.x;
    if (n >= N) return;
    float4 b = ((const float4*)preds)[n];
    int bx = min(BINS - 1, (int)(b.x * INV_CELL));
    int by = min(BINS - 1, (int)(b.y * INV_CELL));
    int pos = atomicAdd(&g_bin_cursor[by * BINS + bx], 1);
    g_sorted[pos] = b;
    g_sorted_idx[pos] = n;
}

// ---------------------------------------------------------------------------
// Phase 1: per-task (GT, slice) partial top-9.
//   key = iou^4 * sigmoid(cls)  — monotone transform of cls^0.2 * iou^0.8
// Every GT has >>9 positive-IoU preds, so zero-IoU pairs never rank.
// ---------------------------------------------------------------------------
__global__ __launch_bounds__(MT) void topk_kernel(
    const float* __restrict__ cls,     // [N,C]
    const float* __restrict__ gtb,     // [G,4]
    const int*   __restrict__ labels,  // [G]
    int C)
{
    const int b = blockIdx.x;
    if (b >= g_total) return;
    const int task  = g_task[b];
    const int g     = task >> 4;
    const int slice = task & 15;
    const int nsl   = g_nsl[g];
    const int4 win  = g_win[g];

    const int tid  = threadIdx.x;
    const int lane = tid & 31;
    const int warp = tid >> 5;
    const int NW   = MT / 32;          // 8 warps

    const float gx1 = gtb[g * 4 + 0];
    const float gy1 = gtb[g * 4 + 1];
    const float gx2 = gtb[g * 4 + 2];
    const float gy2 = gtb[g * 4 + 3];
    const float garea = (gx2 - gx1) * (gy2 - gy1);
    const int lab = labels[g];

    float kv[TOPK];
    int   ki[TOPK];
#pragma unroll
    for (int i = 0; i < TOPK; i++) { kv[i] = -CUDART_INF_F; ki[i] = 0x7fffffff; }
    float vmin = -CUDART_INF_F;

    const int stride = nsl * MT;
    for (int by = win.z; by <= win.w; by++) {
        int s = g_bin_start[by * BINS + win.x];
        int e = g_bin_start[by * BINS + win.y + 1];
        for (int i = s + slice * MT + tid; i < e; i += stride) {
            float4 bb = g_sorted[i];
            float iw = fminf(bb.z, gx2) - fmaxf(bb.x, gx1);
            float ih = fminf(bb.w, gy2) - fmaxf(bb.y, gy1);
            if (iw > 0.0f && ih > 0.0f) {
                int n = g_sorted_idx[i];
                float inter = iw * ih;
                float uni = fmaxf((bb.z - bb.x) * (bb.w - bb.y) + garea - inter, 1e-6f);
                float iou = __fdividef(inter, uni);
                float x   = __ldg(&cls[(long long)n * C + lab]);
                float sig = __fdividef(1.0f, 1.0f + __expf(-x));
                float t2  = iou * iou;
                float key = t2 * t2 * sig;      // (iou^0.8 sig^0.2)^5 — same order
                if (key > vmin) {
                    int am = 0; float mv = kv[0];
#pragma unroll
                    for (int j = 1; j < TOPK; j++) if (kv[j] < mv) { mv = kv[j]; am = j; }
#pragma unroll
                    for (int j = 0; j < TOPK; j++) if (j == am) { kv[j] = key; ki[j] = n; }
                    vmin = kv[0];
#pragma unroll
                    for (int j = 1; j < TOPK; j++) vmin = fminf(vmin, kv[j]);
                }
            }
        }
    }

    // ---- stage 1: per-warp top-9 via 9 argmax rounds ----
    __shared__ float sv2[NW * TOPK];
    __shared__ int   si2[NW * TOPK];

    for (int round = 0; round < TOPK; round++) {
        float bv = -CUDART_INF_F; int bi = 0x7fffffff; int bs = 0;
#pragma unroll
        for (int j = 0; j < TOPK; j++)
            if (kv[j] > bv) { bv = kv[j]; bi = ki[j]; bs = j; }
        float rv = bv; int rix = bi; int rl = lane;
#pragma unroll
        for (int off = 16; off > 0; off >>= 1) {
            float ov = __shfl_down_sync(0xffffffffu, rv, off);
            int   oi = __shfl_down_sync(0xffffffffu, rix, off);
            int   ol = __shfl_down_sync(0xffffffffu, rl, off);
            if (ov > rv || (ov == rv && oi < rix)) { rv = ov; rix = oi; rl = ol; }
        }
        int wlane = __shfl_sync(0xffffffffu, rl, 0);
        if (lane == 0) {
            sv2[warp * TOPK + round] = rv;
            si2[warp * TOPK + round] = rix;
        }
        if (lane == wlane) kv[bs] = -CUDART_INF_F;
    }
    __syncthreads();

    // ---- stage 2: warp 0 merges 72 entries -> slice top-9 -> scratch ----
    const int TOT = NW * TOPK;   // 72
    if (warp == 0) {
        int base = (g * SMAX + slice) * TOPK;
        for (int round = 0; round < TOPK; round++) {
            float bv = -CUDART_INF_F; int bi = 0x7fffffff; int bp = -1;
            for (int j = lane; j < TOT; j += 32) {
                float v = sv2[j];
                if (v > bv || (v == bv && si2[j] < bi)) { bv = v; bi = si2[j]; bp = j; }
            }
#pragma unroll
            for (int off = 16; off > 0; off >>= 1) {
                float ov = __shfl_down_sync(0xffffffffu, bv, off);
                int   oi = __shfl_down_sync(0xffffffffu, bi, off);
                int   op = __shfl_down_sync(0xffffffffu, bp, off);
                if (ov > bv || (ov == bv && oi < bi)) { bv = ov; bi = oi; bp = op; }
            }
            if (lane == 0) {
                g_pv[base + round] = bv;
                g_pi[base + round] = bi;
                if (bp >= 0) sv2[bp] = -CUDART_INF_F;
            }
            __syncwarp();
        }
    }
}

// ---------------------------------------------------------------------------
// Phase 2: one warp per GT — merge nsl*9 partials -> top-9 -> stats -> scatter
// Tail: reset binning counters/extents for next graph replay.
// ---------------------------------------------------------------------------
__global__ __launch_bounds__(32) void merge_kernel(
    const float* __restrict__ points,  // [N,2]
    const float* __restrict__ gtb,     // [G,4]
    float* __restrict__ w)             // [N] zeroed by count_kernel
{
    const int g    = blockIdx.x;
    const int lane = threadIdx.x;
    const int base = g * SMAX * TOPK;
    const int tot  = g_nsl[g] * TOPK;   // <= 72

    float v[3]; int ix[3];
#pragma unroll
    for (int k = 0; k < 3; k++) {
        int j = lane + 32 * k;
        bool in = j < tot;
        v[k]  = in ? g_pv[base + j] : -CUDART_INF_F;
        ix[k] = in ? g_pi[base + j] : 0x7fffffff;
    }

    int fidx[TOPK];
    for (int round = 0; round < TOPK; round++) {
        float bv = v[0]; int bi = ix[0]; int bs = 0;
#pragma unroll
        for (int k = 1; k < 3; k++)
            if (v[k] > bv || (v[k] == bv && ix[k] < bi)) { bv = v[k]; bi = ix[k]; bs = k; }
        int bc = (lane << 2) | bs;
#pragma unroll
        for (int off = 16; off > 0; off >>= 1) {
            float ov = __shfl_down_sync(0xffffffffu, bv, off);
            int   oi = __shfl_down_sync(0xffffffffu, bi, off);
            int   oc = __shfl_down_sync(0xffffffffu, bc, off);
            if (ov > bv || (ov == bv && oi < bi)) { bv = ov; bi = oi; bc = oc; }
        }
        int wc = __shfl_sync(0xffffffffu, bc, 0);
        fidx[round] = __shfl_sync(0xffffffffu, bi, 0);
        if (lane == (wc >> 2)) {
            int s = wc & 3;
            if (s == 0) v[0] = -CUDART_INF_F;
            else if (s == 1) v[1] = -CUDART_INF_F;
            else v[2] = -CUDART_INF_F;
        }
    }

    // ---- fused stats: mean/cov/inverse/maha/valid/scatter-max ----
    int   id = 0x7fffffff;
    float px = 0.0f, py = 0.0f;
    bool  ok = false;
    if (lane < TOPK) {
        id = fidx[lane];
        if (id != 0x7fffffff) {
            ok = true;
            px = points[(long long)id * 2 + 0];
            py = points[(long long)id * 2 + 1];
        }
    }
    float vx = ok ? px : 0.0f, vy = ok ? py : 0.0f;
#pragma unroll
    for (int off = 16; off > 0; off >>= 1) {
        vx += __shfl_down_sync(0xffffffffu, vx, off);
        vy += __shfl_down_sync(0xffffffffu, vy, off);
    }
    const float inv9 = 1.0f / 9.0f;
    float mx = __shfl_sync(0xffffffffu, vx, 0) * inv9;
    float my = __shfl_sync(0xffffffffu, vy, 0) * inv9;

    float dx = ok ? (px - mx) : 0.0f;
    float dy = ok ? (py - my) : 0.0f;
    float sa = dx * dx, sb = dx * dy, sd = dy * dy;
#pragma unroll
    for (int off = 16; off > 0; off >>= 1) {
        sa += __shfl_down_sync(0xffffffffu, sa, off);
        sb += __shfl_down_sync(0xffffffffu, sb, off);
        sd += __shfl_down_sync(0xffffffffu, sd, off);
    }
    float a = __shfl_sync(0xffffffffu, sa, 0) * inv9;
    float b = __shfl_sync(0xffffffffu, sb, 0) * inv9;
    float d = __shfl_sync(0xffffffffu, sd, 0) * inv9;
    float rdn = 1.0f / ((a * d - b * b) + 1e-10f);

    if (ok) {
        float gx1 = gtb[g * 4 + 0];
        float gy1 = gtb[g * 4 + 1];
        float gx2 = gtb[g * 4 + 2];
        float gy2 = gtb[g * 4 + 3];
        float maha = (d * dx * dx - 2.0f * b * dx * dy + a * dy * dy) * rdn;
        float wv = __expf(-0.5f * maha);
        // cy = px (coord 0), cx = py (coord 1); EPS = 1e-10
        bool valid = (py - gx1 > 1e-10f) && (px - gy1 > 1e-10f) &&
                     (gx2 - py > 1e-10f) && (gy2 - px > 1e-10f);
        if (valid && wv > 0.0f)
            atomicMax((int*)&w[id], __float_as_int(wv));  // wv >= 0
    }

    // ---- tail: reset binning state for next launch/replay ----
    int t = g * 32 + lane;
    if (t < NBINS) g_bin_count[t] = 0;
    if (t == 0) { g_maxw_bits = 0u; g_maxh_bits = 0u; }
}

extern "C" void kernel_launch(void* const* d_in, const int* in_sizes, int n_in,
                              void* d_out, int out_size) {
    const float* points = (const float*)d_in[0];   // [N,2]
    const float* cls    = (const float*)d_in[1];   // [N,C]
    const float* preds  = (const float*)d_in[2];   // [N,4]
    const float* gtb    = (const float*)d_in[3];   // [G,4]
    const int*   labels = (const int*)d_in[4];     // [G]

    int N = in_sizes[2] / 4;
    int C = in_sizes[1] / N;
    int G = in_sizes[4];
    float* w = (float*)d_out;

    count_kernel<<<(N + 255) / 256, 256>>>(preds, w, N);
    scan_setup_kernel<<<1, NBINS>>>(gtb, G);
    scatter_kernel<<<(N + 255) / 256, 256>>>(preds, N);
    topk_kernel<<<MAXTASKS, MT>>>(cls, gtb, labels, C);
    merge_kernel<<<G, 32>>>(points, gtb, w);
}

// round 6
// speedup vs baseline: 1.2609x; 1.2609x over previous
#include <cuda_runtime.h>
#include <math_constants.h>

#define TOPK 9
#define BINS 32            // 32x32 grid over [0,1024)^2, cell = 32px
#define NBINS (BINS * BINS)
#define INV_CELL 0.03125f  // 1/32
#define MAXN 131072
#define MAXG 256
#define SMAX 8             // max slices per GT
#define TARGET 1536        // candidates per slice block
#define MAXTASKS (MAXG * SMAX)
#define MT 256             // threads per slice block
#define LISTCAP 5120       // per-block positive-candidate list (u64, 40KB)

// ---------------- device scratch (no allocs allowed) ----------------
// Zero at module load; merge_kernel's tail re-zeros mutable state per replay.
__device__ int      g_bin_count[NBINS];
__device__ int      g_bin_start[NBINS + 1];
__device__ int      g_bin_cursor[NBINS];
__device__ float4   g_sorted[MAXN];
__device__ int      g_sorted_idx[MAXN];
__device__ unsigned g_maxw_bits, g_maxh_bits;
__device__ float    g_pv[MAXG * SMAX * TOPK];   // partial top-9 values
__device__ int      g_pi[MAXG * SMAX * TOPK];   // partial top-9 indices
__device__ int      g_task[MAXTASKS];           // (g<<4)|slice
__device__ int      g_nsl[MAXG];
__device__ int4     g_win[MAXG];                // bx0,bx1,by0,by1
__device__ int      g_total;

// ---------------- pass 1: zero w + smem histogram + max extents ----------------
__global__ __launch_bounds__(256) void count_kernel(
    const float* __restrict__ preds, float* __restrict__ w, int N)
{
    __shared__ int hist[NBINS];
    __shared__ unsigned s_mw, s_mh;
    int tid = threadIdx.x;
#pragma unroll
    for (int i = 0; i < NBINS / 256; i++) hist[tid + i * 256] = 0;
    if (tid == 0) { s_mw = 0u; s_mh = 0u; }
    __syncthreads();

    int n = blockIdx.x * 256 + tid;
    unsigned mw = 0u, mh = 0u;
    if (n < N) {
        w[n] = 0.0f;   // replaces a memset launch
        float4 b = ((const float4*)preds)[n];
        int bx = min(BINS - 1, (int)(b.x * INV_CELL));
        int by = min(BINS - 1, (int)(b.y * INV_CELL));
        atomicAdd(&hist[by * BINS + bx], 1);
        mw = __float_as_uint(b.z - b.x);   // sizes > 0: uint cmp == float cmp
        mh = __float_as_uint(b.w - b.y);
    }
#pragma unroll
    for (int off = 16; off > 0; off >>= 1) {
        mw = max(mw, __shfl_down_sync(0xffffffffu, mw, off));
        mh = max(mh, __shfl_down_sync(0xffffffffu, mh, off));
    }
    if ((tid & 31) == 0) { atomicMax(&s_mw, mw); atomicMax(&s_mh, mh); }
    __syncthreads();

#pragma unroll
    for (int i = 0; i < NBINS / 256; i++) {
        int c = hist[tid + i * 256];
        if (c > 0) atomicAdd(&g_bin_count[tid + i * 256], c);
    }
    if (tid == 0) {
        atomicMax(&g_maxw_bits, s_mw);
        atomicMax(&g_maxh_bits, s_mh);
    }
}

// ---------------- pass 2: bin scan + per-GT window/slice setup + task table ----
__global__ __launch_bounds__(NBINS) void scan_setup_kernel(
    const float* __restrict__ gtb, int G)
{
    __shared__ int sh[NBINS];
    const int t    = threadIdx.x;
    const int lane = t & 31;
    const int warp = t >> 5;

    int c = g_bin_count[t];
    sh[t] = c;
    __syncthreads();
    for (int off = 1; off < NBINS; off <<= 1) {
        int v = (t >= off) ? sh[t - off] : 0;
        __syncthreads();
        sh[t] += v;                      // inclusive scan
        __syncthreads();
    }
    int incl = sh[t];
    g_bin_start[t] = incl - c;
    g_bin_cursor[t] = incl - c;
    if (t == NBINS - 1) g_bin_start[NBINS] = incl;

    // ---- per-GT window + candidate count + slice count (threads 0..255) ----
    int nsl = 0;
    int4 win = make_int4(0, 0, 0, 0);
    if (t < G) {
        float gx1 = gtb[t * 4 + 0];
        float gy1 = gtb[t * 4 + 1];
        float gx2 = gtb[t * 4 + 2];
        float gy2 = gtb[t * 4 + 3];
        float maxw = __uint_as_float(g_maxw_bits);
        float maxh = __uint_as_float(g_maxh_bits);
        int bx0 = max(0, (int)floorf((gx1 - maxw) * INV_CELL));
        int bx1 = min(BINS - 1, (int)(gx2 * INV_CELL));
        int by0 = max(0, (int)floorf((gy1 - maxh) * INV_CELL));
        int by1 = min(BINS - 1, (int)(gy2 * INV_CELL));
        win = make_int4(bx0, bx1, by0, by1);
        int cnt = 0;
        for (int by = by0; by <= by1; by++) {
            int hi = sh[by * BINS + bx1];
            int lo = (by * BINS + bx0 == 0) ? 0 : sh[by * BINS + bx0 - 1];
            cnt += hi - lo;
        }
        nsl = min(SMAX, max(1, (cnt + TARGET - 1) / TARGET));
        g_nsl[t] = nsl;
        g_win[t] = win;
    }

    // ---- prefix sum of nsl over first 256 threads -> task table ----
    __shared__ int wsum[32];
    int v = nsl;
#pragma unroll
    for (int off = 1; off < 32; off <<= 1) {
        int u = __shfl_up_sync(0xffffffffu, v, off);
        if (lane >= off) v += u;
    }
    if (lane == 31) wsum[warp] = v;
    __syncthreads();
    if (warp == 0) {
        int u = wsum[lane];
#pragma unroll
        for (int off = 1; off < 32; off <<= 1) {
            int uu = __shfl_up_sync(0xffffffffu, u, off);
            if (lane >= off) u += uu;
        }
        wsum[lane] = u;
    }
    __syncthreads();
    if (t < 256) {
        int incl_s = v + (warp > 0 ? wsum[warp - 1] : 0);
        int excl_s = incl_s - nsl;
        for (int j = 0; j < nsl; j++)
            g_task[excl_s + j] = (t << 4) | j;
        if (t == 255) g_total = incl_s;
    }
}

// ---------------- pass 3: scatter preds into bin-sorted order ----------------
__global__ __launch_bounds__(256) void scatter_kernel(const float* __restrict__ preds, int N) {
    int n = blockIdx.x * 256 + threadIdx.x;
    if (n >= N) return;
    float4 b = ((const float4*)preds)[n];
    int bx = min(BINS - 1, (int)(b.x * INV_CELL));
    int by = min(BINS - 1, (int)(b.y * INV_CELL));
    int pos = atomicAdd(&g_bin_cursor[by * BINS + bx], 1);
    g_sorted[pos] = b;
    g_sorted_idx[pos] = n;
}

// ---------------------------------------------------------------------------
// Phase 1: per-task (GT, slice) — branchless scan appends positive candidates
// (packed u64: key bits high, ~idx low) to a shared list, then two-stage
// in-block selection extracts the slice top-9.
//   key = iou^4 * sigmoid(cls)  — monotone transform of cls^0.2 * iou^0.8
// ---------------------------------------------------------------------------
__global__ __launch_bounds__(MT) void topk_kernel(
    const float* __restrict__ cls,     // [N,C]
    const float* __restrict__ gtb,     // [G,4]
    const int*   __restrict__ labels,  // [G]
    int C)
{
    __shared__ unsigned long long lst[LISTCAP];
    __shared__ unsigned long long s_part[8 * TOPK];
    __shared__ int s_cnt;

    const int b = blockIdx.x;
    if (b >= g_total) return;
    const int task  = g_task[b];
    const int g     = task >> 4;
    const int slice = task & 15;
    const int nsl   = g_nsl[g];
    const int4 win  = g_win[g];

    const int tid  = threadIdx.x;
    const int lane = tid & 31;
    const int warp = tid >> 5;

    if (tid == 0) s_cnt = 0;
    __syncthreads();

    const float gx1 = gtb[g * 4 + 0];
    const float gy1 = gtb[g * 4 + 1];
    const float gx2 = gtb[g * 4 + 2];
    const float gy2 = gtb[g * 4 + 3];
    const float garea = (gx2 - gx1) * (gy2 - gy1);
    const float* __restrict__ clsl = cls + labels[g];

    const int stride = nsl * MT;
    for (int by = win.z; by <= win.w; by++) {
        int s = g_bin_start[by * BINS + win.x];
        int e = g_bin_start[by * BINS + win.y + 1];
        for (int i = s + slice * MT + tid; i < e; i += stride) {
            // all loads unconditional -> independent across iterations (MLP)
            float4 bb = g_sorted[i];
            int n = g_sorted_idx[i];
            float x = __ldg(&clsl[n * C]);
            float iw = fminf(bb.z, gx2) - fmaxf(bb.x, gx1);
            float ih = fminf(bb.w, gy2) - fmaxf(bb.y, gy1);
            bool pos = (iw > 0.0f) && (ih > 0.0f);
            float inter = iw * ih;
            float uni = fmaxf((bb.z - bb.x) * (bb.w - bb.y) + garea - inter, 1e-6f);
            float iou = __fdividef(inter, uni);
            float sig = __fdividef(1.0f, 1.0f + __expf(-x));
            float t2  = iou * iou;
            float key = t2 * t2 * sig;          // (iou^0.8 sig^0.2)^5 — same order
            if (pos) {
                unsigned long long pk =
                    ((unsigned long long)__float_as_uint(key) << 32) | (unsigned)(~n);
                int p = atomicAdd(&s_cnt, 1);
                if (p < LISTCAP) lst[p] = pk;
            }
        }
    }
    __syncthreads();
    const int L = min(s_cnt, LISTCAP);

    // ---- stage 1: each warp takes top-9 of its strided eighth of the list ----
    for (int round = 0; round < TOPK; round++) {
        unsigned long long best = 0ULL; int bp = -1;
        for (int j = tid; j < L; j += MT) {
            unsigned long long v = lst[j];
            if (v > best) { best = v; bp = j; }
        }
#pragma unroll
        for (int off = 16; off > 0; off >>= 1) {
            unsigned long long ov = __shfl_down_sync(0xffffffffu, best, off);
            int op = __shfl_down_sync(0xffffffffu, bp, off);
            if (ov > best) { best = ov; bp = op; }
        }
        int wp = __shfl_sync(0xffffffffu, bp, 0);
        if (lane == 0) {
            s_part[warp * TOPK + round] = best;
            if (wp >= 0) lst[wp] = 0ULL;   // consume (subset private to this warp)
        }
        __syncwarp();
    }
    __syncthreads();
    if (warp != 0) return;

    // ---- stage 2: warp 0 merges 72 entries -> slice top-9 -> scratch ----
    unsigned long long v0 = (lane < 72) ? s_part[lane] : 0ULL;
    unsigned long long v1 = (lane + 32 < 72) ? s_part[lane + 32] : 0ULL;
    unsigned long long v2 = (lane + 64 < 72) ? s_part[lane + 64] : 0ULL;

    const int base = (g * SMAX + slice) * TOPK;
    for (int round = 0; round < TOPK; round++) {
        unsigned long long best = v0; int bs = 0;
        if (v1 > best) { best = v1; bs = 1; }
        if (v2 > best) { best = v2; bs = 2; }
        int bc = (lane << 2) | bs;
#pragma unroll
        for (int off = 16; off > 0; off >>= 1) {
            unsigned long long ov = __shfl_down_sync(0xffffffffu, best, off);
            int oc = __shfl_down_sync(0xffffffffu, bc, off);
            if (ov > best) { best = ov; bc = oc; }
        }
        int wc = __shfl_sync(0xffffffffu, bc, 0);
        unsigned long long wbest = __shfl_sync(0xffffffffu, best, 0);
        if (lane == round) {
            // this lane records round's winner for the write below
            v0 = v0; // no-op
        }
        if (lane == 0) {
            if (wbest != 0ULL) {
                g_pv[base + round] = __uint_as_float((unsigned)(wbest >> 32));
                g_pi[base + round] = (int)(~(unsigned)(wbest & 0xffffffffu));
            } else {
                g_pv[base + round] = -CUDART_INF_F;
                g_pi[base + round] = 0x7fffffff;
            }
        }
        if (lane == (wc >> 2)) {
            int s = wc & 3;
            if (s == 0) v0 = 0ULL;
            else if (s == 1) v1 = 0ULL;
            else v2 = 0ULL;
        }
        __syncwarp();
    }
}

// ---------------------------------------------------------------------------
// Phase 2: one warp per GT — merge nsl*9 partials -> top-9 -> stats -> scatter
// Tail: reset binning counters/extents for next graph replay.
// ---------------------------------------------------------------------------
__global__ __launch_bounds__(32) void merge_kernel(
    const float* __restrict__ points,  // [N,2]
    const float* __restrict__ gtb,     // [G,4]
    float* __restrict__ w)             // [N] zeroed by count_kernel
{
    const int g    = blockIdx.x;
    const int lane = threadIdx.x;
    const int base = g * SMAX * TOPK;
    const int tot  = g_nsl[g] * TOPK;   // <= 72

    float v[3]; int ix[3];
#pragma unroll
    for (int k = 0; k < 3; k++) {
        int j = lane + 32 * k;
        bool in = j < tot;
        v[k]  = in ? g_pv[base + j] : -CUDART_INF_F;
        ix[k] = in ? g_pi[base + j] : 0x7fffffff;
    }

    int fidx[TOPK];
    for (int round = 0; round < TOPK; round++) {
        float bv = v[0]; int bi = ix[0]; int bs = 0;
#pragma unroll
        for (int k = 1; k < 3; k++)
            if (v[k] > bv || (v[k] == bv && ix[k] < bi)) { bv = v[k]; bi = ix[k]; bs = k; }
        int bc = (lane << 2) | bs;
#pragma unroll
        for (int off = 16; off > 0; off >>= 1) {
            float ov = __shfl_down_sync(0xffffffffu, bv, off);
            int   oi = __shfl_down_sync(0xffffffffu, bi, off);
            int   oc = __shfl_down_sync(0xffffffffu, bc, off);
            if (ov > bv || (ov == bv && oi < bi)) { bv = ov; bi = oi; bc = oc; }
        }
        int wc = __shfl_sync(0xffffffffu, bc, 0);
        fidx[round] = __shfl_sync(0xffffffffu, bi, 0);
        if (lane == (wc >> 2)) {
            int s = wc & 3;
            if (s == 0) v[0] = -CUDART_INF_F;
            else if (s == 1) v[1] = -CUDART_INF_F;
            else v[2] = -CUDART_INF_F;
        }
    }

    // ---- fused stats: mean/cov/inverse/maha/valid/scatter-max ----
    int   id = 0x7fffffff;
    float px = 0.0f, py = 0.0f;
    bool  ok = false;
    if (lane < TOPK) {
        id = fidx[lane];
        if (id != 0x7fffffff) {
            ok = true;
            px = points[(long long)id * 2 + 0];
            py = points[(long long)id * 2 + 1];
        }
    }
    float vx = ok ? px : 0.0f, vy = ok ? py : 0.0f;
#pragma unroll
    for (int off = 16; off > 0; off >>= 1) {
        vx += __shfl_down_sync(0xffffffffu, vx, off);
        vy += __shfl_down_sync(0xffffffffu, vy, off);
    }
    const float inv9 = 1.0f / 9.0f;
    float mx = __shfl_sync(0xffffffffu, vx, 0) * inv9;
    float my = __shfl_sync(0xffffffffu, vy, 0) * inv9;

    float dx = ok ? (px - mx) : 0.0f;
    float dy = ok ? (py - my) : 0.0f;
    float sa = dx * dx, sb = dx * dy, sd = dy * dy;
#pragma unroll
    for (int off = 16; off > 0; off >>= 1) {
        sa += __shfl_down_sync(0xffffffffu, sa, off);
        sb += __shfl_down_sync(0xffffffffu, sb, off);
        sd += __shfl_down_sync(0xffffffffu, sd, off);
    }
    float a = __shfl_sync(0xffffffffu, sa, 0) * inv9;
    float b = __shfl_sync(0xffffffffu, sb, 0) * inv9;
    float d = __shfl_sync(0xffffffffu, sd, 0) * inv9;
    float rdn = 1.0f / ((a * d - b * b) + 1e-10f);

    if (ok) {
        float gx1 = gtb[g * 4 + 0];
        float gy1 = gtb[g * 4 + 1];
        float gx2 = gtb[g * 4 + 2];
        float gy2 = gtb[g * 4 + 3];
        float maha = (d * dx * dx - 2.0f * b * dx * dy + a * dy * dy) * rdn;
        float wv = __expf(-0.5f * maha);
        // cy = px (coord 0), cx = py (coord 1); EPS = 1e-10
        bool valid = (py - gx1 > 1e-10f) && (px - gy1 > 1e-10f) &&
                     (gx2 - py > 1e-10f) && (gy2 - px > 1e-10f);
        if (valid && wv > 0.0f)
            atomicMax((int*)&w[id], __float_as_int(wv));  // wv >= 0
    }

    // ---- tail: reset binning state for next launch/replay ----
    int t = g * 32 + lane;
    if (t < NBINS) g_bin_count[t] = 0;
    if (t == 0) { g_maxw_bits = 0u; g_maxh_bits = 0u; }
}

extern "C" void kernel_launch(void* const* d_in, const int* in_sizes, int n_in,
                              void* d_out, int out_size) {
    const float* points = (const float*)d_in[0];   // [N,2]
    const float* cls    = (const float*)d_in[1];   // [N,C]
    const float* preds  = (const float*)d_in[2];   // [N,4]
    const float* gtb    = (const float*)d_in[3];   // [G,4]
    const int*   labels = (const int*)d_in[4];     // [G]

    int N = in_sizes[2] / 4;
    int C = in_sizes[1] / N;
    int G = in_sizes[4];
    float* w = (float*)d_out;

    count_kernel<<<(N + 255) / 256, 256>>>(preds, w, N);
    scan_setup_kernel<<<1, NBINS>>>(gtb, G);
    scatter_kernel<<<(N + 255) / 256, 256>>>(preds, N);
    topk_kernel<<<MAXTASKS, MT>>>(cls, gtb, labels, C);
    merge_kernel<<<G, 32>>>(points, gtb, w);
}

// round 7
// speedup vs baseline: 1.4105x; 1.1187x over previous
#include <cuda_runtime.h>
#include <math_constants.h>

#define TOPK 9
#define BINS 32            // 32x32 grid over [0,1024)^2, cell = 32px
#define NBINS (BINS * BINS)
#define INV_CELL 0.03125f  // 1/32
#define MAXN 131072
#define MAXG 256
#define SMAX 8             // max slices per GT
#define TARGET 1536        // candidates per slice block
#define MAXTASKS (MAXG * SMAX)
#define MT 256             // threads per slice block
#define NWARP (MT / 32)
#define WCAP 320           // per-warp positive list capacity (u64)

// ---------------- device scratch (no allocs allowed) ----------------
// Zero at module load; merge_kernel's tail re-zeros mutable state per replay.
__device__ int      g_bin_count[NBINS];
__device__ int      g_bin_start[NBINS + 1];
__device__ int      g_bin_cursor[NBINS];
__device__ float4   g_sorted[MAXN];
__device__ int      g_sorted_idx[MAXN];
__device__ unsigned g_maxw_bits, g_maxh_bits;
__device__ float    g_pv[MAXG * SMAX * TOPK];   // partial top-9 values
__device__ int      g_pi[MAXG * SMAX * TOPK];   // partial top-9 indices
__device__ int      g_task[MAXTASKS];           // (g<<4)|slice
__device__ int      g_nsl[MAXG];
__device__ int4     g_win[MAXG];                // bx0,bx1,by0,by1
__device__ int      g_total;

// ---------------- pass 1: zero w + smem histogram + max extents ----------------
__global__ __launch_bounds__(256) void count_kernel(
    const float* __restrict__ preds, float* __restrict__ w, int N)
{
    __shared__ int hist[NBINS];
    __shared__ unsigned s_mw, s_mh;
    int tid = threadIdx.x;
#pragma unroll
    for (int i = 0; i < NBINS / 256; i++) hist[tid + i * 256] = 0;
    if (tid == 0) { s_mw = 0u; s_mh = 0u; }
    __syncthreads();

    int n = blockIdx.x * 256 + tid;
    unsigned mw = 0u, mh = 0u;
    if (n < N) {
        w[n] = 0.0f;   // replaces a memset launch
        float4 b = ((const float4*)preds)[n];
        int bx = min(BINS - 1, (int)(b.x * INV_CELL));
        int by = min(BINS - 1, (int)(b.y * INV_CELL));
        atomicAdd(&hist[by * BINS + bx], 1);
        mw = __float_as_uint(b.z - b.x);   // sizes > 0: uint cmp == float cmp
        mh = __float_as_uint(b.w - b.y);
    }
#pragma unroll
    for (int off = 16; off > 0; off >>= 1) {
        mw = max(mw, __shfl_down_sync(0xffffffffu, mw, off));
        mh = max(mh, __shfl_down_sync(0xffffffffu, mh, off));
    }
    if ((tid & 31) == 0) { atomicMax(&s_mw, mw); atomicMax(&s_mh, mh); }
    __syncthreads();

#pragma unroll
    for (int i = 0; i < NBINS / 256; i++) {
        int c = hist[tid + i * 256];
        if (c > 0) atomicAdd(&g_bin_count[tid + i * 256], c);
    }
    if (tid == 0) {
        atomicMax(&g_maxw_bits, s_mw);
        atomicMax(&g_maxh_bits, s_mh);
    }
}

// ---------------- pass 2: bin scan + per-GT window/slice setup + task table ----
__global__ __launch_bounds__(NBINS) void scan_setup_kernel(
    const float* __restrict__ gtb, int G)
{
    __shared__ int sh[NBINS];
    const int t    = threadIdx.x;
    const int lane = t & 31;
    const int warp = t >> 5;

    int c = g_bin_count[t];
    sh[t] = c;
    __syncthreads();
    for (int off = 1; off < NBINS; off <<= 1) {
        int v = (t >= off) ? sh[t - off] : 0;
        __syncthreads();
        sh[t] += v;                      // inclusive scan
        __syncthreads();
    }
    int incl = sh[t];
    g_bin_start[t] = incl - c;
    g_bin_cursor[t] = incl - c;
    if (t == NBINS - 1) g_bin_start[NBINS] = incl;

    // ---- per-GT window + candidate count + slice count (threads 0..255) ----
    int nsl = 0;
    int4 win = make_int4(0, 0, 0, 0);
    if (t < G) {
        float gx1 = gtb[t * 4 + 0];
        float gy1 = gtb[t * 4 + 1];
        float gx2 = gtb[t * 4 + 2];
        float gy2 = gtb[t * 4 + 3];
        float maxw = __uint_as_float(g_maxw_bits);
        float maxh = __uint_as_float(g_maxh_bits);
        int bx0 = max(0, (int)floorf((gx1 - maxw) * INV_CELL));
        int bx1 = min(BINS - 1, (int)(gx2 * INV_CELL));
        int by0 = max(0, (int)floorf((gy1 - maxh) * INV_CELL));
        int by1 = min(BINS - 1, (int)(gy2 * INV_CELL));
        win = make_int4(bx0, bx1, by0, by1);
        int cnt = 0;
        for (int by = by0; by <= by1; by++) {
            int hi = sh[by * BINS + bx1];
            int lo = (by * BINS + bx0 == 0) ? 0 : sh[by * BINS + bx0 - 1];
            cnt += hi - lo;
        }
        nsl = min(SMAX, max(1, (cnt + TARGET - 1) / TARGET));
        g_nsl[t] = nsl;
        g_win[t] = win;
    }

    // ---- prefix sum of nsl over first 256 threads -> task table ----
    __shared__ int wsum[32];
    int v = nsl;
#pragma unroll
    for (int off = 1; off < 32; off <<= 1) {
        int u = __shfl_up_sync(0xffffffffu, v, off);
        if (lane >= off) v += u;
    }
    if (lane == 31) wsum[warp] = v;
    __syncthreads();
    if (warp == 0) {
        int u = wsum[lane];
#pragma unroll
        for (int off = 1; off < 32; off <<= 1) {
            int uu = __shfl_up_sync(0xffffffffu, u, off);
            if (lane >= off) u += uu;
        }
        wsum[lane] = u;
    }
    __syncthreads();
    if (t < 256) {
        int incl_s = v + (warp > 0 ? wsum[warp - 1] : 0);
        int excl_s = incl_s - nsl;
        for (int j = 0; j < nsl; j++)
            g_task[excl_s + j] = (t << 4) | j;
        if (t == 255) g_total = incl_s;
    }
}

// ---------------- pass 3: scatter preds into bin-sorted order ----------------
__global__ __launch_bounds__(256) void scatter_kernel(const float* __restrict__ preds, int N) {
    int n = blockIdx.x * 256 + threadIdx.x;
    if (n >= N) return;
    float4 b = ((const float4*)preds)[n];
    int bx = min(BINS - 1, (int)(b.x * INV_CELL));
    int by = min(BINS - 1, (int)(b.y * INV_CELL));
    int pos = atomicAdd(&g_bin_cursor[by * BINS + bx], 1);
    g_sorted[pos] = b;
    g_sorted_idx[pos] = n;
}

// ---------------------------------------------------------------------------
// Phase 1: per-task (GT, slice) — branchless scan appends positive candidates
// (packed u64: key bits high, ~idx low) to a WARP-PRIVATE shared list using
// ballot/popc offsets (no atomics). Each warp then selects its own top-9;
// warp 0 merges 72 entries -> slice top-9.
//   key = iou^4 * sigmoid(cls)  — monotone transform of cls^0.2 * iou^0.8
// ---------------------------------------------------------------------------
__global__ __launch_bounds__(MT) void topk_kernel(
    const float* __restrict__ cls,     // [N,C]
    const float* __restrict__ gtb,     // [G,4]
    const int*   __restrict__ labels,  // [G]
    int C)
{
    __shared__ unsigned long long lst[NWARP * WCAP];   // 20KB
    __shared__ unsigned long long s_part[NWARP * TOPK];

    const int b = blockIdx.x;
    if (b >= g_total) return;
    const int task  = g_task[b];
    const int g     = task >> 4;
    const int slice = task & 15;
    const int nsl   = g_nsl[g];
    const int4 win  = g_win[g];

    const int tid  = threadIdx.x;
    const int lane = tid & 31;
    const int warp = tid >> 5;

    const float gx1 = gtb[g * 4 + 0];
    const float gy1 = gtb[g * 4 + 1];
    const float gx2 = gtb[g * 4 + 2];
    const float gy2 = gtb[g * 4 + 3];
    const float garea = (gx2 - gx1) * (gy2 - gy1);
    const float* __restrict__ clsl = cls + labels[g];

    unsigned long long* ml = &lst[warp * WCAP];
    int cnt = 0;                         // warp-uniform list length

    const int stride = nsl * MT;
    const int lead = slice * MT + warp * 32;   // warp-uniform lead offset
    for (int by = win.z; by <= win.w; by++) {
        int s = g_bin_start[by * BINS + win.x];
        int e = g_bin_start[by * BINS + win.y + 1];
        // warp-uniform loop bound; lanes predicate on i < e
        for (int base_i = s + lead; base_i < e; base_i += stride) {
            int i = base_i + lane;
            bool inb = i < e;
            float4 bb;
            int n = 0;
            float x = 0.0f;
            if (inb) {
                bb = g_sorted[i];
                n  = g_sorted_idx[i];
                x  = __ldg(&clsl[n * C]);
            } else {
                bb = make_float4(0.f, 0.f, 0.f, 0.f);
            }
            float iw = fminf(bb.z, gx2) - fmaxf(bb.x, gx1);
            float ih = fminf(bb.w, gy2) - fmaxf(bb.y, gy1);
            bool pos = inb && (iw > 0.0f) && (ih > 0.0f);
            float inter = iw * ih;
            float uni = fmaxf((bb.z - bb.x) * (bb.w - bb.y) + garea - inter, 1e-6f);
            float iou = __fdividef(inter, uni);
            float sig = __fdividef(1.0f, 1.0f + __expf(-x));
            float t2  = iou * iou;
            float key = t2 * t2 * sig;       // (iou^0.8 sig^0.2)^5 — same order
            unsigned mask = __ballot_sync(0xffffffffu, pos);
            if (pos) {
                int off = cnt + __popc(mask & ((1u << lane) - 1u));
                if (off < WCAP) {
                    unsigned long long pk =
                        ((unsigned long long)__float_as_uint(key) << 32) | (unsigned)(~n);
                    ml[off] = pk;
                }
            }
            cnt += __popc(mask);
        }
    }
    const int cw = min(cnt, WCAP);

    // ---- stage 1: each warp takes top-9 of its private list ----
    for (int round = 0; round < TOPK; round++) {
        unsigned long long best = 0ULL; int bp = -1;
        for (int j = lane; j < cw; j += 32) {
            unsigned long long v = ml[j];
            if (v > best) { best = v; bp = j; }
        }
#pragma unroll
        for (int off = 16; off > 0; off >>= 1) {
            unsigned long long ov = __shfl_down_sync(0xffffffffu, best, off);
            int op = __shfl_down_sync(0xffffffffu, bp, off);
            if (ov > best) { best = ov; bp = op; }
        }
        int wp = __shfl_sync(0xffffffffu, bp, 0);
        if (lane == 0) {
            s_part[warp * TOPK + round] = best;
            if (wp >= 0) ml[wp] = 0ULL;   // consume (warp-private)
        }
        __syncwarp();
    }
    __syncthreads();
    if (warp != 0) return;

    // ---- stage 2: warp 0 merges 72 entries -> slice top-9 -> scratch ----
    unsigned long long v0 = (lane < NWARP * TOPK) ? s_part[lane] : 0ULL;
    unsigned long long v1 = (lane + 32 < NWARP * TOPK) ? s_part[lane + 32] : 0ULL;
    unsigned long long v2 = (lane + 64 < NWARP * TOPK) ? s_part[lane + 64] : 0ULL;

    const int base = (g * SMAX + slice) * TOPK;
    for (int round = 0; round < TOPK; round++) {
        unsigned long long best = v0; int bs = 0;
        if (v1 > best) { best = v1; bs = 1; }
        if (v2 > best) { best = v2; bs = 2; }
        int bc = (lane << 2) | bs;
#pragma unroll
        for (int off = 16; off > 0; off >>= 1) {
            unsigned long long ov = __shfl_down_sync(0xffffffffu, best, off);
            int oc = __shfl_down_sync(0xffffffffu, bc, off);
            if (ov > best) { best = ov; bc = oc; }
        }
        int wc = __shfl_sync(0xffffffffu, bc, 0);
        unsigned long long wbest = __shfl_sync(0xffffffffu, best, 0);
        if (lane == 0) {
            if (wbest != 0ULL) {
                g_pv[base + round] = __uint_as_float((unsigned)(wbest >> 32));
                g_pi[base + round] = (int)(~(unsigned)(wbest & 0xffffffffu));
            } else {
                g_pv[base + round] = -CUDART_INF_F;
                g_pi[base + round] = 0x7fffffff;
            }
        }
        if (lane == (wc >> 2)) {
            int s = wc & 3;
            if (s == 0) v0 = 0ULL;
            else if (s == 1) v1 = 0ULL;
            else v2 = 0ULL;
        }
        __syncwarp();
    }
}

// ---------------------------------------------------------------------------
// Phase 2: one warp per GT — merge nsl*9 partials -> top-9 -> stats -> scatter
// Tail: reset binning counters/extents for next graph replay.
// ---------------------------------------------------------------------------
__global__ __launch_bounds__(32) void merge_kernel(
    const float* __restrict__ points,  // [N,2]
    const float* __restrict__ gtb,     // [G,4]
    float* __restrict__ w)             // [N] zeroed by count_kernel
{
    const int g    = blockIdx.x;
    const int lane = threadIdx.x;
    const int base = g * SMAX * TOPK;
    const int tot  = g_nsl[g] * TOPK;   // <= 72

    float v[3]; int ix[3];
#pragma unroll
    for (int k = 0; k < 3; k++) {
        int j = lane + 32 * k;
        bool in = j < tot;
        v[k]  = in ? g_pv[base + j] : -CUDART_INF_F;
        ix[k] = in ? g_pi[base + j] : 0x7fffffff;
    }

    int fidx[TOPK];
    for (int round = 0; round < TOPK; round++) {
        float bv = v[0]; int bi = ix[0]; int bs = 0;
#pragma unroll
        for (int k = 1; k < 3; k++)
            if (v[k] > bv || (v[k] == bv && ix[k] < bi)) { bv = v[k]; bi = ix[k]; bs = k; }
        int bc = (lane << 2) | bs;
#pragma unroll
        for (int off = 16; off > 0; off >>= 1) {
            float ov = __shfl_down_sync(0xffffffffu, bv, off);
            int   oi = __shfl_down_sync(0xffffffffu, bi, off);
            int   oc = __shfl_down_sync(0xffffffffu, bc, off);
            if (ov > bv || (ov == bv && oi < bi)) { bv = ov; bi = oi; bc = oc; }
        }
        int wc = __shfl_sync(0xffffffffu, bc, 0);
        fidx[round] = __shfl_sync(0xffffffffu, bi, 0);
        if (lane == (wc >> 2)) {
            int s = wc & 3;
            if (s == 0) v[0] = -CUDART_INF_F;
            else if (s == 1) v[1] = -CUDART_INF_F;
            else v[2] = -CUDART_INF_F;
        }
    }

    // ---- fused stats: mean/cov/inverse/maha/valid/scatter-max ----
    int   id = 0x7fffffff;
    float px = 0.0f, py = 0.0f;
    bool  ok = false;
    if (lane < TOPK) {
        id = fidx[lane];
        if (id != 0x7fffffff) {
            ok = true;
            px = points[(long long)id * 2 + 0];
            py = points[(long long)id * 2 + 1];
        }
    }
    float vx = ok ? px : 0.0f, vy = ok ? py : 0.0f;
#pragma unroll
    for (int off = 16; off > 0; off >>= 1) {
        vx += __shfl_down_sync(0xffffffffu, vx, off);
        vy += __shfl_down_sync(0xffffffffu, vy, off);
    }
    const float inv9 = 1.0f / 9.0f;
    float mx = __shfl_sync(0xffffffffu, vx, 0) * inv9;
    float my = __shfl_sync(0xffffffffu, vy, 0) * inv9;

    float dx = ok ? (px - mx) : 0.0f;
    float dy = ok ? (py - my) : 0.0f;
    float sa = dx * dx, sb = dx * dy, sd = dy * dy;
#pragma unroll
    for (int off = 16; off > 0; off >>= 1) {
        sa += __shfl_down_sync(0xffffffffu, sa, off);
        sb += __shfl_down_sync(0xffffffffu, sb, off);
        sd += __shfl_down_sync(0xffffffffu, sd, off);
    }
    float a = __shfl_sync(0xffffffffu, sa, 0) * inv9;
    float b = __shfl_sync(0xffffffffu, sb, 0) * inv9;
    float d = __shfl_sync(0xffffffffu, sd, 0) * inv9;
    float rdn = 1.0f / ((a * d - b * b) + 1e-10f);

    if (ok) {
        float gx1 = gtb[g * 4 + 0];
        float gy1 = gtb[g * 4 + 1];
        float gx2 = gtb[g * 4 + 2];
        float gy2 = gtb[g * 4 + 3];
        float maha = (d * dx * dx - 2.0f * b * dx * dy + a * dy * dy) * rdn;
        float wv = __expf(-0.5f * maha);
        // cy = px (coord 0), cx = py (coord 1); EPS = 1e-10
        bool valid = (py - gx1 > 1e-10f) && (px - gy1 > 1e-10f) &&
                     (gx2 - py > 1e-10f) && (gy2 - px > 1e-10f);
        if (valid && wv > 0.0f)
            atomicMax((int*)&w[id], __float_as_int(wv));  // wv >= 0
    }

    // ---- tail: reset binning state for next launch/replay ----
    int t = g * 32 + lane;
    if (t < NBINS) g_bin_count[t] = 0;
    if (t == 0) { g_maxw_bits = 0u; g_maxh_bits = 0u; }
}

extern "C" void kernel_launch(void* const* d_in, const int* in_sizes, int n_in,
                              void* d_out, int out_size) {
    const float* points = (const float*)d_in[0];   // [N,2]
    const float* cls    = (const float*)d_in[1];   // [N,C]
    const float* preds  = (const float*)d_in[2];   // [N,4]
    const float* gtb    = (const float*)d_in[3];   // [G,4]
    const int*   labels = (const int*)d_in[4];     // [G]

    int N = in_sizes[2] / 4;
    int C = in_sizes[1] / N;
    int G = in_sizes[4];
    float* w = (float*)d_out;

    count_kernel<<<(N + 255) / 256, 256>>>(preds, w, N);
    scan_setup_kernel<<<1, NBINS>>>(gtb, G);
    scatter_kernel<<<(N + 255) / 256, 256>>>(preds, N);
    topk_kernel<<<MAXTASKS, MT>>>(cls, gtb, labels, C);
    merge_kernel<<<G, 32>>>(points, gtb, w);
}